// round 3
// baseline (speedup 1.0000x reference)
#include <cuda_runtime.h>
#include <math.h>

#define BB     8
#define C_IN   100
#define C_HID  200
#define HH     256
#define WW     256
#define TILE_W 128
#define NTHR   400

// Intermediate activation scratch: [B, C_HID, H, W] fp32 (419 MB, static device mem)
__device__ float g_h[(size_t)BB * C_HID * HH * WW];

static const int SMEM1 = (C_IN  * TILE_W + C_IN  * C_HID) * 4;  // 131200 B
static const int SMEM2 = (C_HID * TILE_W + C_HID * C_IN ) * 4;  // 182400 B

__device__ __forceinline__ unsigned long long pack2(float lo, float hi) {
    unsigned long long r;
    asm("mov.b64 %0, {%1, %2};" : "=l"(r) : "f"(lo), "f"(hi));
    return r;
}
__device__ __forceinline__ void unpack2(unsigned long long v, float& lo, float& hi) {
    asm("mov.b64 {%0, %1}, %2;" : "=f"(lo), "=f"(hi) : "l"(v));
}
__device__ __forceinline__ void fma2(unsigned long long& d,
                                     unsigned long long a,
                                     unsigned long long b) {
    asm("fma.rn.f32x2 %0, %1, %2, %0;" : "+l"(d) : "l"(a), "l"(b));
}

__device__ __forceinline__ float gelu_exact(float v) {
    return 0.5f * v * (1.0f + erff(v * 0.70710678118654752440f));
}

// ---------------------------------------------------------------------------
// Layer 1: h = gelu(W1 @ shift(x) + b1)    K=100 -> N=200
// ---------------------------------------------------------------------------
__global__ __launch_bounds__(NTHR) void shift_mlp_l1(
    const float* __restrict__ x,
    const float* __restrict__ w1,
    const float* __restrict__ b1)
{
    extern __shared__ float sm[];
    float* xs_s = sm;                    // [C_IN][TILE_W]
    float* w_s  = sm + C_IN * TILE_W;    // [C_IN][C_HID]  (k-major)

    const int xt  = blockIdx.x * TILE_W;
    const int y   = blockIdx.y;
    const int b   = blockIdx.z;
    const int tid = threadIdx.x;

    // Load W1 transposed into smem: w_s[k][o] = w1[o][k]  (gmem coalesced)
    for (int i = tid; i < C_IN * C_HID; i += NTHR) {
        int o = i / C_IN;
        int k = i - o * C_IN;
        w_s[k * C_HID + o] = w1[i];
    }
    // Load shifted x tile. groups of 20 channels: +x, -x, +y, -y, identity
    for (int i = tid; i < C_IN * TILE_W; i += NTHR) {
        int c  = i >> 7;        // / TILE_W
        int ix = i & (TILE_W - 1);
        int g  = c / 20;
        int yy = y + (g == 2) - (g == 3);
        int xx = xt + ix + (g == 0) - (g == 1);
        float v = 0.0f;
        if ((unsigned)yy < HH && (unsigned)xx < WW)
            v = x[(((size_t)b * C_IN + c) * HH + yy) * WW + xx];
        xs_s[c * TILE_W + ix] = v;
    }
    __syncthreads();

    const int tm = tid & 15;     // 0..15 (pixels)
    const int tn = tid >> 4;     // 0..24 (outputs)
    const int mA = tm * 4, mB = 64 + tm * 4;
    const int oA = tn * 4, oB = 100 + tn * 4;

    unsigned long long acc[4][8];   // [pixel-pair][output]
    #pragma unroll
    for (int i = 0; i < 4; i++)
        #pragma unroll
        for (int j = 0; j < 8; j++) acc[i][j] = 0ULL;

    #pragma unroll 2
    for (int k = 0; k < C_IN; k++) {
        const float* xr = &xs_s[k * TILE_W];
        ulonglong2 a0 = *(const ulonglong2*)(xr + mA);
        ulonglong2 a1 = *(const ulonglong2*)(xr + mB);
        unsigned long long xp[4] = {a0.x, a0.y, a1.x, a1.y};
        const float* wr = &w_s[k * C_HID];
        float4 wv0 = *(const float4*)(wr + oA);
        float4 wv1 = *(const float4*)(wr + oB);
        float wf[8] = {wv0.x, wv0.y, wv0.z, wv0.w, wv1.x, wv1.y, wv1.z, wv1.w};
        #pragma unroll
        for (int j = 0; j < 8; j++) {
            unsigned long long wp = pack2(wf[j], wf[j]);
            #pragma unroll
            for (int i = 0; i < 4; i++) fma2(acc[i][j], xp[i], wp);
        }
    }

    // Epilogue: bias + exact gelu, store to g_h
    #pragma unroll
    for (int j = 0; j < 8; j++) {
        int o = (j < 4) ? (oA + j) : (oB + j - 4);
        float bias = __ldg(&b1[o]);
        float* hp = &g_h[(((size_t)b * C_HID + o) * HH + y) * WW + xt];
        #pragma unroll
        for (int i = 0; i < 4; i++) {
            int m = (i < 2) ? (mA + i * 2) : (mB + (i - 2) * 2);
            float lo, hi;
            unpack2(acc[i][j], lo, hi);
            lo = gelu_exact(lo + bias);
            hi = gelu_exact(hi + bias);
            hp[m]     = lo;
            hp[m + 1] = hi;
        }
    }
}

// ---------------------------------------------------------------------------
// Layer 2: out = W2 @ shift(h) + b2        K=200 -> N=100
// ---------------------------------------------------------------------------
__global__ __launch_bounds__(NTHR) void shift_mlp_l2(
    const float* __restrict__ w2,
    const float* __restrict__ b2,
    float* __restrict__ out)
{
    extern __shared__ float sm[];
    float* xs_s = sm;                     // [C_HID][TILE_W]
    float* w_s  = sm + C_HID * TILE_W;    // [C_HID][C_IN]  (k-major)

    const int xt  = blockIdx.x * TILE_W;
    const int y   = blockIdx.y;
    const int b   = blockIdx.z;
    const int tid = threadIdx.x;

    for (int i = tid; i < C_HID * C_IN; i += NTHR) {
        int o = i / C_HID;
        int k = i - o * C_HID;
        w_s[k * C_IN + o] = w2[i];
    }
    // Shifted h tile. groups of 40 channels.
    for (int i = tid; i < C_HID * TILE_W; i += NTHR) {
        int c  = i >> 7;
        int ix = i & (TILE_W - 1);
        int g  = c / 40;
        int yy = y + (g == 2) - (g == 3);
        int xx = xt + ix + (g == 0) - (g == 1);
        float v = 0.0f;
        if ((unsigned)yy < HH && (unsigned)xx < WW)
            v = g_h[(((size_t)b * C_HID + c) * HH + yy) * WW + xx];
        xs_s[c * TILE_W + ix] = v;
    }
    __syncthreads();

    const int tm = tid & 15;
    const int tn = tid >> 4;     // 0..24
    const int mA = tm * 4, mB = 64 + tm * 4;
    const int oA = tn * 2, oB = 50 + tn * 2;

    unsigned long long acc[4][4];
    #pragma unroll
    for (int i = 0; i < 4; i++)
        #pragma unroll
        for (int j = 0; j < 4; j++) acc[i][j] = 0ULL;

    #pragma unroll 2
    for (int k = 0; k < C_HID; k++) {
        const float* xr = &xs_s[k * TILE_W];
        ulonglong2 a0 = *(const ulonglong2*)(xr + mA);
        ulonglong2 a1 = *(const ulonglong2*)(xr + mB);
        unsigned long long xp[4] = {a0.x, a0.y, a1.x, a1.y};
        const float* wr = &w_s[k * C_IN];
        float2 wv0 = *(const float2*)(wr + oA);
        float2 wv1 = *(const float2*)(wr + oB);
        float wf[4] = {wv0.x, wv0.y, wv1.x, wv1.y};
        #pragma unroll
        for (int j = 0; j < 4; j++) {
            unsigned long long wp = pack2(wf[j], wf[j]);
            #pragma unroll
            for (int i = 0; i < 4; i++) fma2(acc[i][j], xp[i], wp);
        }
    }

    #pragma unroll
    for (int j = 0; j < 4; j++) {
        int o = (j < 2) ? (oA + j) : (oB + j - 2);
        float bias = __ldg(&b2[o]);
        float* op = &out[(((size_t)b * C_IN + o) * HH + y) * WW + xt];
        #pragma unroll
        for (int i = 0; i < 4; i++) {
            int m = (i < 2) ? (mA + i * 2) : (mB + (i - 2) * 2);
            float lo, hi;
            unpack2(acc[i][j], lo, hi);
            op[m]     = lo + bias;
            op[m + 1] = hi + bias;
        }
    }
}

// ---------------------------------------------------------------------------
extern "C" void kernel_launch(void* const* d_in, const int* in_sizes, int n_in,
                              void* d_out, int out_size)
{
    const float* x  = (const float*)d_in[0];
    const float* w1 = (const float*)d_in[1];
    const float* b1 = (const float*)d_in[2];
    const float* w2 = (const float*)d_in[3];
    const float* b2 = (const float*)d_in[4];
    float* out = (float*)d_out;

    // Opt-in large dynamic smem (idempotent, not a stream op; capture-safe)
    cudaFuncSetAttribute(shift_mlp_l1, cudaFuncAttributeMaxDynamicSharedMemorySize, SMEM1);
    cudaFuncSetAttribute(shift_mlp_l2, cudaFuncAttributeMaxDynamicSharedMemorySize, SMEM2);

    dim3 grid(WW / TILE_W, HH, BB);   // (2, 256, 8)
    shift_mlp_l1<<<grid, NTHR, SMEM1>>>(x, w1, b1);
    shift_mlp_l2<<<grid, NTHR, SMEM2>>>(w2, b2, out);
}